// round 7
// baseline (speedup 1.0000x reference)
#include <cuda_runtime.h>
#include <math_constants.h>

typedef unsigned int u32;
typedef unsigned long long u64;

#define NPTS 3600
#define DD   128
#define HH   512
#define WW   512
#define NPB  900
#define WC   30
#define SCOLS 3601   // 1 + NPTS

// ---------------- scratch (static device globals) ---------------------------
__device__ int   g_y1[NPTS], g_x1[NPTS];
__device__ int   g_yd[NPTS], g_xd[NPTS];
__device__ int   g_xy2x[NPTS], g_xy2y[NPTS];
__device__ float g_A[NPTS * DD];
__device__ float g_B[NPTS * DD];

__constant__ int c_OI[13] = {-2,-1,-1,-1, 0, 0, 0, 0, 0, 1, 1, 1, 2};
__constant__ int c_OJ[13] = { 0,-1, 0, 1,-2,-1, 0, 1, 2,-1, 0, 1, 0};

// ---------------- f32x2 packed-FMA helpers ----------------------------------
__device__ __forceinline__ void fma2(u64& d, u64 a, u64 b)
{
    asm("fma.rn.f32x2 %0, %1, %2, %0;" : "+l"(d) : "l"(a), "l"(b));
}
__device__ __forceinline__ u64 pack2(float x, float y)
{
    u64 d;
    asm("mov.b64 %0, {%1, %2};" : "=l"(d) : "r"(__float_as_uint(x)), "r"(__float_as_uint(y)));
    return d;
}
__device__ __forceinline__ void unpack2(u64 v, float& x, float& y)
{
    u32 a, b;
    asm("mov.b64 {%0, %1}, %2;" : "=r"(a), "=r"(b) : "l"(v));
    x = __uint_as_float(a);
    y = __uint_as_float(b);
}

// ---------------- kernel 1: per-cell argmax sample + descriptor gather ------
__global__ void k_sample(const float* __restrict__ det1, const float* __restrict__ des1,
                         const float* __restrict__ det2, const float* __restrict__ des2)
{
    const int c = blockIdx.x;
    const int which = blockIdx.y;
    const float* det = which ? det2 : det1;
    const float* des = which ? des2 : des1;

    const int b = c / NPB;
    const int cell = c % NPB;
    const int hc = cell / WC;
    const int wc = cell % WC;
    const int t = threadIdx.x;
    const int row = 16 + hc * 16 + (t >> 4);
    const int col = 16 + wc * 16 + (t & 15);

    float v = det[((size_t)b * HH + row) * WW + col];

    __shared__ float sv[256];
    __shared__ int   si[256];
    sv[t] = v;
    si[t] = t;
    __syncthreads();
    for (int s = 128; s > 0; s >>= 1) {
        if (t < s) {
            float v2 = sv[t + s];
            int i2 = si[t + s];
            if (v2 > sv[t] || (v2 == sv[t] && i2 < si[t])) { sv[t] = v2; si[t] = i2; }
        }
        __syncthreads();
    }
    const int best = si[0];
    const int brow = 16 + hc * 16 + (best >> 4);  // axis3 index (x1 / xd)
    const int bcol = 16 + wc * 16 + (best & 15);  // axis2 index (y1 / yd)

    if (t == 0) {
        if (which == 0) { g_y1[c] = bcol; g_x1[c] = brow; }
        else            { g_yd[c] = bcol; g_xd[c] = brow; }
    }
    if (t < DD) {
        float d = des[(((size_t)b * DD + t) * HH + bcol) * WW + brow];
        if (which == 0) g_A[(size_t)c * DD + t] = d;
        else            g_B[(size_t)c * DD + t] = d;
    }
}

// ---------------- kernel 2: neighbor matching (one warp per keypoint) -------
__global__ void k_match(const float* __restrict__ des2, const float* __restrict__ aflow,
                        const float* __restrict__ qlt1, const float* __restrict__ qlt2,
                        float* __restrict__ out_scores, float* __restrict__ out_lab,
                        float* __restrict__ out_mask, float* __restrict__ out_qlt)
{
    const int warp = threadIdx.x >> 5;
    const int lane = threadIdx.x & 31;
    const int n = blockIdx.x * 4 + warp;
    if (n >= NPTS) return;

    const int b  = n / NPB;
    const int y1 = g_y1[n];
    const int x1 = g_x1[n];

    const float s0 = g_A[(size_t)n * DD + lane];
    const float s1 = g_A[(size_t)n * DD + lane + 32];
    const float s2 = g_A[(size_t)n * DD + lane + 64];
    const float s3 = g_A[(size_t)n * DD + lane + 96];

    const float ax = aflow[(((size_t)b * 2 + 0) * HH + y1) * WW + x1];
    const float ay = aflow[(((size_t)b * 2 + 1) * HH + y1) * WW + x1];
    const int xx = (int)(ax + 0.5f);
    const int yy = (int)(ay + 0.5f);
    const bool msk = (xx >= 0) && (yy >= 0) && (xx < WW) && (yy < HH);

    const float* db = des2 + (size_t)b * DD * HH * WW;
    const size_t plane = (size_t)HH * WW;

    float best = -CUDART_INF_F;
    int pos = 0;
    #pragma unroll
    for (int k = 0; k < 13; k++) {
        int px = xx + c_OI[k]; px = px < 0 ? 0 : (px > WW - 1 ? WW - 1 : px);
        int py = yy + c_OJ[k]; py = py < 0 ? 0 : (py > HH - 1 ? HH - 1 : py);
        const float* p = db + (size_t)py * WW + px;
        float dot = s0 * p[(size_t)lane * plane]
                  + s1 * p[(size_t)(lane + 32) * plane]
                  + s2 * p[(size_t)(lane + 64) * plane]
                  + s3 * p[(size_t)(lane + 96) * plane];
        #pragma unroll
        for (int off = 16; off > 0; off >>= 1)
            dot += __shfl_xor_sync(0xffffffffu, dot, off);
        if (dot > best) { best = dot; pos = k; }
    }

    if (lane == 0) {
        int sx = xx + c_OI[pos]; sx = sx < 0 ? 0 : (sx > WW - 1 ? WW - 1 : sx);
        int sy = yy + c_OJ[pos]; sy = sy < 0 ? 0 : (sy > HH - 1 ? HH - 1 : sy);
        float q = 0.5f * (qlt1[((size_t)b * HH + y1) * WW + x1] +
                          qlt2[((size_t)b * HH + sy) * WW + sx]);
        out_scores[(size_t)n * SCOLS] = best;
        out_lab[(size_t)n * SCOLS]    = 1.0f;
        out_qlt[n]  = q;
        out_mask[n] = msk ? 1.0f : 0.0f;
        g_xy2x[n] = xx;
        g_xy2y[n] = yy;
    }
}

// ---------------- kernel 3: f32x2 GEMM (A @ B^T) + mask + labels ------------
// Block 128x128, 256 threads, 8x8 per-thread tile, K chunk 8, pitch-132 smem.
__global__ void __launch_bounds__(256, 1)
k_gemm(float* __restrict__ out_scores, float* __restrict__ out_lab)
{
    __shared__ float As[8][132];
    __shared__ float Bs[8][132];

    const int tid = threadIdx.x;
    const int tx = tid & 15;        // n direction
    const int ty = tid >> 4;        // m direction
    const int m0 = blockIdx.y * 128;
    const int n0 = blockIdx.x * 128;

    const int lr = tid >> 1;        // 0..127 row to load
    const int kq = (tid & 1) * 4;   // 0 or 4

    // acc[m][p] holds the pair {C[m][2p], C[m][2p+1]}
    u64 acc[8][4];
    #pragma unroll
    for (int m = 0; m < 8; m++) {
        #pragma unroll
        for (int p = 0; p < 4; p++) acc[m][p] = 0ull;
    }

    for (int kc = 0; kc < DD; kc += 8) {
        float4 av = make_float4(0.f, 0.f, 0.f, 0.f);
        float4 bv = av;
        if (m0 + lr < NPTS) av = *(const float4*)&g_A[(size_t)(m0 + lr) * DD + kc + kq];
        if (n0 + lr < NPTS) bv = *(const float4*)&g_B[(size_t)(n0 + lr) * DD + kc + kq];
        __syncthreads();
        As[kq + 0][lr] = av.x; As[kq + 1][lr] = av.y;
        As[kq + 2][lr] = av.z; As[kq + 3][lr] = av.w;
        Bs[kq + 0][lr] = bv.x; Bs[kq + 1][lr] = bv.y;
        Bs[kq + 2][lr] = bv.z; Bs[kq + 3][lr] = bv.w;
        __syncthreads();

        #pragma unroll
        for (int j = 0; j < 8; j++) {
            float4 a0 = *(const float4*)&As[j][ty * 8];
            float4 a1 = *(const float4*)&As[j][ty * 8 + 4];
            float4 b0 = *(const float4*)&Bs[j][tx * 8];
            float4 b1 = *(const float4*)&Bs[j][tx * 8 + 4];
            u64 bp[4];
            bp[0] = pack2(b0.x, b0.y);
            bp[1] = pack2(b0.z, b0.w);
            bp[2] = pack2(b1.x, b1.y);
            bp[3] = pack2(b1.z, b1.w);
            float am[8];
            am[0] = a0.x; am[1] = a0.y; am[2] = a0.z; am[3] = a0.w;
            am[4] = a1.x; am[5] = a1.y; am[6] = a1.z; am[7] = a1.w;
            #pragma unroll
            for (int m = 0; m < 8; m++) {
                u64 as = pack2(am[m], am[m]);
                fma2(acc[m][0], as, bp[0]);
                fma2(acc[m][1], as, bp[1]);
                fma2(acc[m][2], as, bp[2]);
                fma2(acc[m][3], as, bp[3]);
            }
        }
    }

    // ---- epilogue: distance mask, write scores[:,1:] and labels[:,1:]=0 ----
    int rX[8], rY[8], rBt[8], rI[8];
    #pragma unroll
    for (int m = 0; m < 8; m++) {
        int i = m0 + ty * 8 + m;
        rI[m] = (i < NPTS) ? i : -1;
        int iw = (i < NPTS) ? i : 0;
        rX[m] = g_xy2x[iw];
        rY[m] = g_xy2y[iw];
        rBt[m] = iw / NPB;
    }
    int cX[8], cY[8], cBt[8], cJ[8];
    #pragma unroll
    for (int nn = 0; nn < 8; nn++) {
        int j = n0 + tx * 8 + nn;
        cJ[nn] = (j < NPTS) ? j : -1;
        int jw = (j < NPTS) ? j : 0;
        cX[nn] = g_xd[jw];
        cY[nn] = g_yd[jw];
        cBt[nn] = jw / NPB;
    }

    #pragma unroll
    for (int m = 0; m < 8; m++) {
        if (rI[m] < 0) continue;
        const size_t rowbase = (size_t)rI[m] * SCOLS + 1;
        #pragma unroll
        for (int p = 0; p < 4; p++) {
            float c0, c1;
            unpack2(acc[m][p], c0, c1);
            #pragma unroll
            for (int e = 0; e < 2; e++) {
                int nn = 2 * p + e;
                int j = cJ[nn];
                if (j < 0) continue;
                int dx = cX[nn] - rX[m];
                int dy = cY[nn] - rY[m];
                int dis2 = dx * dx + dy * dy + ((cBt[nn] != rBt[m]) ? 4 : 0);
                float vout = (dis2 < 4) ? 0.f : (e ? c1 : c0);
                out_scores[rowbase + j] = vout;
                out_lab[rowbase + j] = 0.0f;
            }
        }
    }
}

// ---------------- launch ----------------------------------------------------
extern "C" void kernel_launch(void* const* d_in, const int* in_sizes, int n_in,
                              void* d_out, int out_size)
{
    const float* des1  = (const float*)d_in[0];
    const float* det1  = (const float*)d_in[1];
    const float* qlt1  = (const float*)d_in[2];
    const float* des2  = (const float*)d_in[3];
    const float* det2  = (const float*)d_in[4];
    const float* qlt2  = (const float*)d_in[5];
    const float* aflow = (const float*)d_in[6];

    float* out        = (float*)d_out;
    float* out_scores = out;                                     // (3600, 3601)
    float* out_lab    = out + (size_t)NPTS * SCOLS;              // (3600, 3601)
    float* out_mask   = out_lab + (size_t)NPTS * SCOLS;          // (4, 900)
    float* out_qlt    = out_mask + NPTS;                         // (3600, 1)

    dim3 gs(NPTS, 2);
    k_sample<<<gs, 256>>>(det1, des1, det2, des2);

    k_match<<<NPTS / 4, 128>>>(des2, aflow, qlt1, qlt2, out_scores, out_lab, out_mask, out_qlt);

    dim3 gg((NPTS + 127) / 128, (NPTS + 127) / 128);
    k_gemm<<<gg, 256>>>(out_scores, out_lab);
}

// round 8
// speedup vs baseline: 1.4176x; 1.4176x over previous
#include <cuda_runtime.h>
#include <cuda_bf16.h>

typedef unsigned int u32;

#define NPTS 3600
#define DD   128
#define HH   512
#define WW   512
#define NPB  900
#define WC   30
#define SCOLS 3601   // 1 + NPTS
#define SPITCH 40    // bf16 elements per smem row (conflict-free)

// ---------------- scratch (static device globals) ---------------------------
__device__ int   g_y1[NPTS], g_x1[NPTS];
__device__ int   g_yd[NPTS], g_xd[NPTS];
__device__ int   g_xy2x[NPTS], g_xy2y[NPTS];
__device__ float g_A[NPTS * DD];
// bf16 hi/lo planes stored as uint4 arrays (16B alignment guaranteed)
__device__ uint4 g_Ahi[NPTS * DD / 8];
__device__ uint4 g_Alo[NPTS * DD / 8];
__device__ uint4 g_Bhi[NPTS * DD / 8];
__device__ uint4 g_Blo[NPTS * DD / 8];

__constant__ int c_OI[13] = {-2,-1,-1,-1, 0, 0, 0, 0, 0, 1, 1, 1, 2};
__constant__ int c_OJ[13] = { 0,-1, 0, 1,-2,-1, 0, 1, 2,-1, 0, 1, 0};

// ---------------- kernel 1: per-cell argmax sample + descriptor gather ------
__global__ void k_sample(const float* __restrict__ det1, const float* __restrict__ des1,
                         const float* __restrict__ det2, const float* __restrict__ des2)
{
    const int c = blockIdx.x;
    const int which = blockIdx.y;
    const float* det = which ? det2 : det1;
    const float* des = which ? des2 : des1;

    const int b = c / NPB;
    const int cell = c % NPB;
    const int hc = cell / WC;
    const int wc = cell % WC;
    const int t = threadIdx.x;
    const int row = 16 + hc * 16 + (t >> 4);
    const int col = 16 + wc * 16 + (t & 15);

    float v = det[((size_t)b * HH + row) * WW + col];

    __shared__ float sv[256];
    __shared__ int   si[256];
    sv[t] = v;
    si[t] = t;
    __syncthreads();
    for (int s = 128; s > 0; s >>= 1) {
        if (t < s) {
            float v2 = sv[t + s];
            int i2 = si[t + s];
            if (v2 > sv[t] || (v2 == sv[t] && i2 < si[t])) { sv[t] = v2; si[t] = i2; }
        }
        __syncthreads();
    }
    const int best = si[0];
    const int brow = 16 + hc * 16 + (best >> 4);  // axis3 index (x1 / xd)
    const int bcol = 16 + wc * 16 + (best & 15);  // axis2 index (y1 / yd)

    if (t == 0) {
        if (which == 0) { g_y1[c] = bcol; g_x1[c] = brow; }
        else            { g_yd[c] = bcol; g_xd[c] = brow; }
    }
    if (t < DD) {
        float d = des[(((size_t)b * DD + t) * HH + bcol) * WW + brow];
        __nv_bfloat16 hi = __float2bfloat16(d);
        __nv_bfloat16 lo = __float2bfloat16(d - __bfloat162float(hi));
        const size_t idx = (size_t)c * DD + t;
        if (which == 0) {
            g_A[idx] = d;
            ((__nv_bfloat16*)g_Ahi)[idx] = hi;
            ((__nv_bfloat16*)g_Alo)[idx] = lo;
        } else {
            ((__nv_bfloat16*)g_Bhi)[idx] = hi;
            ((__nv_bfloat16*)g_Blo)[idx] = lo;
        }
    }
}

// ---------------- kernel 2: neighbor matching (one warp per keypoint) -------
__global__ void k_match(const float* __restrict__ des2, const float* __restrict__ aflow,
                        const float* __restrict__ qlt1, const float* __restrict__ qlt2,
                        float* __restrict__ out_scores, float* __restrict__ out_lab,
                        float* __restrict__ out_mask, float* __restrict__ out_qlt)
{
    const int warp = threadIdx.x >> 5;
    const int lane = threadIdx.x & 31;
    const int n = blockIdx.x * 4 + warp;
    if (n >= NPTS) return;

    const int b  = n / NPB;
    const int y1 = g_y1[n];
    const int x1 = g_x1[n];

    const float s0 = g_A[(size_t)n * DD + lane];
    const float s1 = g_A[(size_t)n * DD + lane + 32];
    const float s2 = g_A[(size_t)n * DD + lane + 64];
    const float s3 = g_A[(size_t)n * DD + lane + 96];

    const float ax = aflow[(((size_t)b * 2 + 0) * HH + y1) * WW + x1];
    const float ay = aflow[(((size_t)b * 2 + 1) * HH + y1) * WW + x1];
    const int xx = (int)(ax + 0.5f);
    const int yy = (int)(ay + 0.5f);
    const bool msk = (xx >= 0) && (yy >= 0) && (xx < WW) && (yy < HH);

    const float* db = des2 + (size_t)b * DD * HH * WW;
    const size_t plane = (size_t)HH * WW;

    float best = -3.402823466e+38f;
    int pos = 0;
    #pragma unroll
    for (int k = 0; k < 13; k++) {
        int px = xx + c_OI[k]; px = px < 0 ? 0 : (px > WW - 1 ? WW - 1 : px);
        int py = yy + c_OJ[k]; py = py < 0 ? 0 : (py > HH - 1 ? HH - 1 : py);
        const float* p = db + (size_t)py * WW + px;
        float dot = s0 * p[(size_t)lane * plane]
                  + s1 * p[(size_t)(lane + 32) * plane]
                  + s2 * p[(size_t)(lane + 64) * plane]
                  + s3 * p[(size_t)(lane + 96) * plane];
        #pragma unroll
        for (int off = 16; off > 0; off >>= 1)
            dot += __shfl_xor_sync(0xffffffffu, dot, off);
        if (dot > best) { best = dot; pos = k; }
    }

    if (lane == 0) {
        int sx = xx + c_OI[pos]; sx = sx < 0 ? 0 : (sx > WW - 1 ? WW - 1 : sx);
        int sy = yy + c_OJ[pos]; sy = sy < 0 ? 0 : (sy > HH - 1 ? HH - 1 : sy);
        float q = 0.5f * (qlt1[((size_t)b * HH + y1) * WW + x1] +
                          qlt2[((size_t)b * HH + sy) * WW + sx]);
        out_scores[(size_t)n * SCOLS] = best;
        out_lab[(size_t)n * SCOLS]    = 1.0f;
        out_qlt[n]  = q;
        out_mask[n] = msk ? 1.0f : 0.0f;
        g_xy2x[n] = xx;
        g_xy2y[n] = yy;
    }
}

// ---------------- kernel 3: bf16x3 tensor-core GEMM + mask + labels --------
__device__ __forceinline__ void mma_bf16(float* c, const u32* a, const u32* b)
{
    asm volatile("mma.sync.aligned.m16n8k16.row.col.f32.bf16.bf16.f32 "
                 "{%0,%1,%2,%3}, {%4,%5,%6,%7}, {%8,%9}, {%0,%1,%2,%3};"
                 : "+f"(c[0]), "+f"(c[1]), "+f"(c[2]), "+f"(c[3])
                 : "r"(a[0]), "r"(a[1]), "r"(a[2]), "r"(a[3]), "r"(b[0]), "r"(b[1]));
}

__global__ void __launch_bounds__(256, 1)
k_gemm(float* __restrict__ out_scores, float* __restrict__ out_lab)
{
    __shared__ __align__(16) __nv_bfloat16 sAhi[128 * SPITCH];
    __shared__ __align__(16) __nv_bfloat16 sAlo[128 * SPITCH];
    __shared__ __align__(16) __nv_bfloat16 sBhi[128 * SPITCH];
    __shared__ __align__(16) __nv_bfloat16 sBlo[128 * SPITCH];

    const int tid    = threadIdx.x;
    const int warp   = tid >> 5;
    const int lane   = tid & 31;
    const int warp_m = warp >> 2;      // 0..1
    const int warp_n = warp & 3;       // 0..3
    const int m0 = blockIdx.y * 128;
    const int n0 = blockIdx.x * 128;

    const int g  = lane >> 2;          // fragment group row 0..7
    const int cp = (lane & 3) * 2;     // fragment col pair 0,2,4,6

    float acc[4][4][4];
    #pragma unroll
    for (int mt = 0; mt < 4; mt++) {
        #pragma unroll
        for (int nt = 0; nt < 4; nt++) {
            acc[mt][nt][0] = 0.f; acc[mt][nt][1] = 0.f;
            acc[mt][nt][2] = 0.f; acc[mt][nt][3] = 0.f;
        }
    }

    const int lr = tid >> 1;            // 0..127: tile row to load
    const int kh = (tid & 1) * 16;      // 16-elem half of the 32-k chunk

    for (int kc = 0; kc < DD; kc += 32) {
        __syncthreads();
        // Each thread fills 16 bf16 (TWO uint4) per array: [kh, kh+16) of row lr.
        uint4 z = make_uint4(0u, 0u, 0u, 0u);
        uint4 vah0 = z, vah1 = z, vlo0 = z, vlo1 = z;
        uint4 vbh0 = z, vbh1 = z, vbl0 = z, vbl1 = z;
        const int ar = m0 + lr;
        const int br = n0 + lr;
        const int gi = (kc + kh) >> 3;              // uint4 index within row
        if (ar < NPTS) {
            vah0 = g_Ahi[(size_t)ar * (DD / 8) + gi];
            vah1 = g_Ahi[(size_t)ar * (DD / 8) + gi + 1];
            vlo0 = g_Alo[(size_t)ar * (DD / 8) + gi];
            vlo1 = g_Alo[(size_t)ar * (DD / 8) + gi + 1];
        }
        if (br < NPTS) {
            vbh0 = g_Bhi[(size_t)br * (DD / 8) + gi];
            vbh1 = g_Bhi[(size_t)br * (DD / 8) + gi + 1];
            vbl0 = g_Blo[(size_t)br * (DD / 8) + gi];
            vbl1 = g_Blo[(size_t)br * (DD / 8) + gi + 1];
        }
        *(uint4*)&sAhi[lr * SPITCH + kh]     = vah0;
        *(uint4*)&sAhi[lr * SPITCH + kh + 8] = vah1;
        *(uint4*)&sAlo[lr * SPITCH + kh]     = vlo0;
        *(uint4*)&sAlo[lr * SPITCH + kh + 8] = vlo1;
        *(uint4*)&sBhi[lr * SPITCH + kh]     = vbh0;
        *(uint4*)&sBhi[lr * SPITCH + kh + 8] = vbh1;
        *(uint4*)&sBlo[lr * SPITCH + kh]     = vbl0;
        *(uint4*)&sBlo[lr * SPITCH + kh + 8] = vbl1;
        __syncthreads();

        #pragma unroll
        for (int ks = 0; ks < 32; ks += 16) {
            u32 Ahf[4][4];
            u32 Alf[4][4];
            u32 Bhf[4][2];
            u32 Blf[4][2];

            // A fragments per PTX spec: a0=A[g][c],a1=A[g+8][c],a2=A[g][c+8],a3=A[g+8][c+8]
            #pragma unroll
            for (int mt = 0; mt < 4; mt++) {
                const int r0 = warp_m * 64 + mt * 16 + g;
                const int r8 = r0 + 8;
                const int c0 = ks + cp;
                Ahf[mt][0] = *(const u32*)&sAhi[r0 * SPITCH + c0];
                Ahf[mt][1] = *(const u32*)&sAhi[r8 * SPITCH + c0];
                Ahf[mt][2] = *(const u32*)&sAhi[r0 * SPITCH + c0 + 8];
                Ahf[mt][3] = *(const u32*)&sAhi[r8 * SPITCH + c0 + 8];
                Alf[mt][0] = *(const u32*)&sAlo[r0 * SPITCH + c0];
                Alf[mt][1] = *(const u32*)&sAlo[r8 * SPITCH + c0];
                Alf[mt][2] = *(const u32*)&sAlo[r0 * SPITCH + c0 + 8];
                Alf[mt][3] = *(const u32*)&sAlo[r8 * SPITCH + c0 + 8];
            }
            // B fragments: b0={Bs[n=g][k=cp..cp+1]}, b1={Bs[n=g][k=cp+8..cp+9]}
            #pragma unroll
            for (int nt = 0; nt < 4; nt++) {
                const int rn = warp_n * 32 + nt * 8 + g;
                const int c0 = ks + cp;
                Bhf[nt][0] = *(const u32*)&sBhi[rn * SPITCH + c0];
                Bhf[nt][1] = *(const u32*)&sBhi[rn * SPITCH + c0 + 8];
                Blf[nt][0] = *(const u32*)&sBlo[rn * SPITCH + c0];
                Blf[nt][1] = *(const u32*)&sBlo[rn * SPITCH + c0 + 8];
            }
            #pragma unroll
            for (int mt = 0; mt < 4; mt++) {
                #pragma unroll
                for (int nt = 0; nt < 4; nt++) {
                    mma_bf16(acc[mt][nt], Ahf[mt], Bhf[nt]);
                    mma_bf16(acc[mt][nt], Ahf[mt], Blf[nt]);
                    mma_bf16(acc[mt][nt], Alf[mt], Bhf[nt]);
                }
            }
        }
    }

    // ---- epilogue: distance mask, write scores[:,1:] and labels[:,1:]=0 ----
    // C fragment: c0=C[g][cp], c1=C[g][cp+1], c2=C[g+8][cp], c3=C[g+8][cp+1]
    int rX[8], rY[8], rB[8], rI[8];
    #pragma unroll
    for (int idx = 0; idx < 8; idx++) {
        int mt = idx >> 1;
        int h  = idx & 1;
        int i  = m0 + warp_m * 64 + mt * 16 + g + h * 8;
        rI[idx] = (i < NPTS) ? i : -1;
        int iw = (i < NPTS) ? i : 0;
        rX[idx] = g_xy2x[iw];
        rY[idx] = g_xy2y[iw];
        rB[idx] = iw / NPB;
    }
    int cX[8], cY[8], cB[8], cJ[8];
    #pragma unroll
    for (int idx = 0; idx < 8; idx++) {
        int nt = idx >> 1;
        int e  = idx & 1;
        int j  = n0 + warp_n * 32 + nt * 8 + cp + e;
        cJ[idx] = (j < NPTS) ? j : -1;
        int jw = (j < NPTS) ? j : 0;
        cX[idx] = g_xd[jw];
        cY[idx] = g_yd[jw];
        cB[idx] = jw / NPB;
    }

    #pragma unroll
    for (int mt = 0; mt < 4; mt++) {
        #pragma unroll
        for (int nt = 0; nt < 4; nt++) {
            #pragma unroll
            for (int r = 0; r < 4; r++) {
                int ridx = mt * 2 + (r >> 1);   // row: g (+8 if r>=2)
                int cidx = nt * 2 + (r & 1);    // col: cp + (r&1)
                int i = rI[ridx];
                int j = cJ[cidx];
                if (i < 0 || j < 0) continue;
                int dx = cX[cidx] - rX[ridx];
                int dy = cY[cidx] - rY[ridx];
                int dis2 = dx * dx + dy * dy + ((cB[cidx] != rB[ridx]) ? 4 : 0);
                float vout = (dis2 < 4) ? 0.f : acc[mt][nt][r];
                size_t o = (size_t)i * SCOLS + 1 + j;
                out_scores[o] = vout;
                out_lab[o] = 0.0f;
            }
        }
    }
}

// ---------------- launch ----------------------------------------------------
extern "C" void kernel_launch(void* const* d_in, const int* in_sizes, int n_in,
                              void* d_out, int out_size)
{
    const float* des1  = (const float*)d_in[0];
    const float* det1  = (const float*)d_in[1];
    const float* qlt1  = (const float*)d_in[2];
    const float* des2  = (const float*)d_in[3];
    const float* det2  = (const float*)d_in[4];
    const float* qlt2  = (const float*)d_in[5];
    const float* aflow = (const float*)d_in[6];

    float* out        = (float*)d_out;
    float* out_scores = out;                                     // (3600, 3601)
    float* out_lab    = out + (size_t)NPTS * SCOLS;              // (3600, 3601)
    float* out_mask   = out_lab + (size_t)NPTS * SCOLS;          // (4, 900)
    float* out_qlt    = out_mask + NPTS;                         // (3600, 1)

    dim3 gs(NPTS, 2);
    k_sample<<<gs, 256>>>(det1, des1, det2, des2);

    k_match<<<NPTS / 4, 128>>>(des2, aflow, qlt1, qlt2, out_scores, out_lab, out_mask, out_qlt);

    dim3 gg((NPTS + 127) / 128, (NPTS + 127) / 128);
    k_gemm<<<gg, 256>>>(out_scores, out_lab);
}

// round 10
// speedup vs baseline: 1.8453x; 1.3018x over previous
#include <cuda_runtime.h>
#include <cuda_bf16.h>

typedef unsigned int u32;

#define NPTS 3600
#define DD   128
#define HH   512
#define WW   512
#define NPB  900
#define WC   30
#define SCOLS 3601   // 1 + NPTS
#define SPITCH 40    // bf16 elements per smem row (conflict-free)

// ---------------- scratch (static device globals) ---------------------------
__device__ int   g_y1[NPTS], g_x1[NPTS];
__device__ int   g_yd[NPTS], g_xd[NPTS];
__device__ int   g_xy2x[NPTS], g_xy2y[NPTS];
__device__ float g_A[NPTS * DD];
// bf16 hi/lo planes stored as uint4 arrays (16B alignment guaranteed)
__device__ uint4 g_Ahi[NPTS * DD / 8];
__device__ uint4 g_Alo[NPTS * DD / 8];
__device__ uint4 g_Bhi[NPTS * DD / 8];
__device__ uint4 g_Blo[NPTS * DD / 8];

__constant__ int c_OI[13] = {-2,-1,-1,-1, 0, 0, 0, 0, 0, 1, 1, 1, 2};
__constant__ int c_OJ[13] = { 0,-1, 0, 1,-2,-1, 0, 1, 2,-1, 0, 1, 0};

// ---------------- kernel 1: per-cell argmax sample + descriptor gather ------
__global__ void k_sample(const float* __restrict__ det1, const float* __restrict__ des1,
                         const float* __restrict__ det2, const float* __restrict__ des2)
{
    const int c = blockIdx.x;
    const int which = blockIdx.y;
    const float* det = which ? det2 : det1;
    const float* des = which ? des2 : des1;

    const int b = c / NPB;
    const int cell = c % NPB;
    const int hc = cell / WC;
    const int wc = cell % WC;
    const int t = threadIdx.x;
    const int row = 16 + hc * 16 + (t >> 4);
    const int col = 16 + wc * 16 + (t & 15);

    float v = det[((size_t)b * HH + row) * WW + col];

    __shared__ float sv[256];
    __shared__ int   si[256];
    sv[t] = v;
    si[t] = t;
    __syncthreads();
    for (int s = 128; s > 0; s >>= 1) {
        if (t < s) {
            float v2 = sv[t + s];
            int i2 = si[t + s];
            if (v2 > sv[t] || (v2 == sv[t] && i2 < si[t])) { sv[t] = v2; si[t] = i2; }
        }
        __syncthreads();
    }
    const int best = si[0];
    const int brow = 16 + hc * 16 + (best >> 4);  // axis3 index (x1 / xd)
    const int bcol = 16 + wc * 16 + (best & 15);  // axis2 index (y1 / yd)

    if (t == 0) {
        if (which == 0) { g_y1[c] = bcol; g_x1[c] = brow; }
        else            { g_yd[c] = bcol; g_xd[c] = brow; }
    }
    if (t < DD) {
        float d = des[(((size_t)b * DD + t) * HH + bcol) * WW + brow];
        __nv_bfloat16 hi = __float2bfloat16(d);
        __nv_bfloat16 lo = __float2bfloat16(d - __bfloat162float(hi));
        const size_t idx = (size_t)c * DD + t;
        if (which == 0) {
            g_A[idx] = d;
            ((__nv_bfloat16*)g_Ahi)[idx] = hi;
            ((__nv_bfloat16*)g_Alo)[idx] = lo;
        } else {
            ((__nv_bfloat16*)g_Bhi)[idx] = hi;
            ((__nv_bfloat16*)g_Blo)[idx] = lo;
        }
    }
}

// ---------------- kernel 2: neighbor matching (one BLOCK per keypoint) ------
// 128 threads = 128 descriptor channels; 13 neighbor loads per thread issued
// independently (MLP=13), then 13 warp-reductions + 4x13 smem reduce.
__global__ void __launch_bounds__(128)
k_match(const float* __restrict__ des2, const float* __restrict__ aflow,
        const float* __restrict__ qlt1, const float* __restrict__ qlt2,
        float* __restrict__ out_scores, float* __restrict__ out_lab,
        float* __restrict__ out_mask, float* __restrict__ out_qlt)
{
    const int n = blockIdx.x;
    const int t = threadIdx.x;        // d channel 0..127
    const int lane = t & 31;
    const int warp = t >> 5;

    const int b  = n / NPB;
    const int y1 = g_y1[n];
    const int x1 = g_x1[n];

    const float s = g_A[(size_t)n * DD + t];

    const float ax = aflow[(((size_t)b * 2 + 0) * HH + y1) * WW + x1];
    const float ay = aflow[(((size_t)b * 2 + 1) * HH + y1) * WW + x1];
    const int xx = (int)(ax + 0.5f);
    const int yy = (int)(ay + 0.5f);

    const float* base = des2 + (size_t)b * DD * HH * WW + (size_t)t * HH * WW;

    float val[13];
    #pragma unroll
    for (int k = 0; k < 13; k++) {
        int px = xx + c_OI[k]; px = px < 0 ? 0 : (px > WW - 1 ? WW - 1 : px);
        int py = yy + c_OJ[k]; py = py < 0 ? 0 : (py > HH - 1 ? HH - 1 : py);
        val[k] = s * __ldg(&base[(size_t)py * WW + px]);
    }

    // warp-level reduction of all 13 partial dots
    #pragma unroll
    for (int k = 0; k < 13; k++) {
        #pragma unroll
        for (int off = 16; off > 0; off >>= 1)
            val[k] += __shfl_xor_sync(0xffffffffu, val[k], off);
    }

    __shared__ float sred[4][13];
    if (lane == 0) {
        #pragma unroll
        for (int k = 0; k < 13; k++) sred[warp][k] = val[k];
    }
    __syncthreads();

    if (t == 0) {
        float dots[13];
        #pragma unroll
        for (int k = 0; k < 13; k++)
            dots[k] = sred[0][k] + sred[1][k] + sred[2][k] + sred[3][k];

        float best = dots[0];
        int pos = 0;
        #pragma unroll
        for (int k = 1; k < 13; k++)
            if (dots[k] > best) { best = dots[k]; pos = k; }

        const bool msk = (xx >= 0) && (yy >= 0) && (xx < WW) && (yy < HH);
        int sx = xx + c_OI[pos]; sx = sx < 0 ? 0 : (sx > WW - 1 ? WW - 1 : sx);
        int sy = yy + c_OJ[pos]; sy = sy < 0 ? 0 : (sy > HH - 1 ? HH - 1 : sy);
        float q = 0.5f * (qlt1[((size_t)b * HH + y1) * WW + x1] +
                          qlt2[((size_t)b * HH + sy) * WW + sx]);
        out_scores[(size_t)n * SCOLS] = best;
        out_lab[(size_t)n * SCOLS]    = 1.0f;
        out_qlt[n]  = q;
        out_mask[n] = msk ? 1.0f : 0.0f;
        g_xy2x[n] = xx;
        g_xy2y[n] = yy;
    }
}

// ---------------- kernel 3: bf16x3 tensor-core GEMM + mask + labels --------
__device__ __forceinline__ void mma_bf16(float* c, const u32* a, const u32* b)
{
    asm volatile("mma.sync.aligned.m16n8k16.row.col.f32.bf16.bf16.f32 "
                 "{%0,%1,%2,%3}, {%4,%5,%6,%7}, {%8,%9}, {%0,%1,%2,%3};"
                 : "+f"(c[0]), "+f"(c[1]), "+f"(c[2]), "+f"(c[3])
                 : "r"(a[0]), "r"(a[1]), "r"(a[2]), "r"(a[3]), "r"(b[0]), "r"(b[1]));
}

__global__ void __launch_bounds__(256, 1)
k_gemm(float* __restrict__ out_scores, float* __restrict__ out_lab)
{
    __shared__ __align__(16) __nv_bfloat16 sAhi[128 * SPITCH];
    __shared__ __align__(16) __nv_bfloat16 sAlo[128 * SPITCH];
    __shared__ __align__(16) __nv_bfloat16 sBhi[128 * SPITCH];
    __shared__ __align__(16) __nv_bfloat16 sBlo[128 * SPITCH];

    const int tid    = threadIdx.x;
    const int warp   = tid >> 5;
    const int lane   = tid & 31;
    const int warp_m = warp >> 2;      // 0..1
    const int warp_n = warp & 3;       // 0..3
    const int m0 = blockIdx.y * 128;
    const int n0 = blockIdx.x * 128;

    const int g  = lane >> 2;          // fragment group row 0..7
    const int cp = (lane & 3) * 2;     // fragment col pair 0,2,4,6

    float acc[4][4][4];
    #pragma unroll
    for (int mt = 0; mt < 4; mt++) {
        #pragma unroll
        for (int nt = 0; nt < 4; nt++) {
            acc[mt][nt][0] = 0.f; acc[mt][nt][1] = 0.f;
            acc[mt][nt][2] = 0.f; acc[mt][nt][3] = 0.f;
        }
    }

    const int lr = tid >> 1;            // 0..127: tile row to load
    const int kh = (tid & 1) * 16;      // 16-elem half of the 32-k chunk

    for (int kc = 0; kc < DD; kc += 32) {
        __syncthreads();
        uint4 z = make_uint4(0u, 0u, 0u, 0u);
        uint4 vah0 = z, vah1 = z, vlo0 = z, vlo1 = z;
        uint4 vbh0 = z, vbh1 = z, vbl0 = z, vbl1 = z;
        const int ar = m0 + lr;
        const int br = n0 + lr;
        const int gi = (kc + kh) >> 3;              // uint4 index within row
        if (ar < NPTS) {
            vah0 = g_Ahi[(size_t)ar * (DD / 8) + gi];
            vah1 = g_Ahi[(size_t)ar * (DD / 8) + gi + 1];
            vlo0 = g_Alo[(size_t)ar * (DD / 8) + gi];
            vlo1 = g_Alo[(size_t)ar * (DD / 8) + gi + 1];
        }
        if (br < NPTS) {
            vbh0 = g_Bhi[(size_t)br * (DD / 8) + gi];
            vbh1 = g_Bhi[(size_t)br * (DD / 8) + gi + 1];
            vbl0 = g_Blo[(size_t)br * (DD / 8) + gi];
            vbl1 = g_Blo[(size_t)br * (DD / 8) + gi + 1];
        }
        *(uint4*)&sAhi[lr * SPITCH + kh]     = vah0;
        *(uint4*)&sAhi[lr * SPITCH + kh + 8] = vah1;
        *(uint4*)&sAlo[lr * SPITCH + kh]     = vlo0;
        *(uint4*)&sAlo[lr * SPITCH + kh + 8] = vlo1;
        *(uint4*)&sBhi[lr * SPITCH + kh]     = vbh0;
        *(uint4*)&sBhi[lr * SPITCH + kh + 8] = vbh1;
        *(uint4*)&sBlo[lr * SPITCH + kh]     = vbl0;
        *(uint4*)&sBlo[lr * SPITCH + kh + 8] = vbl1;
        __syncthreads();

        #pragma unroll
        for (int ks = 0; ks < 32; ks += 16) {
            u32 Ahf[4][4];
            u32 Alf[4][4];
            u32 Bhf[4][2];
            u32 Blf[4][2];

            #pragma unroll
            for (int mt = 0; mt < 4; mt++) {
                const int r0 = warp_m * 64 + mt * 16 + g;
                const int r8 = r0 + 8;
                const int c0 = ks + cp;
                Ahf[mt][0] = *(const u32*)&sAhi[r0 * SPITCH + c0];
                Ahf[mt][1] = *(const u32*)&sAhi[r8 * SPITCH + c0];
                Ahf[mt][2] = *(const u32*)&sAhi[r0 * SPITCH + c0 + 8];
                Ahf[mt][3] = *(const u32*)&sAhi[r8 * SPITCH + c0 + 8];
                Alf[mt][0] = *(const u32*)&sAlo[r0 * SPITCH + c0];
                Alf[mt][1] = *(const u32*)&sAlo[r8 * SPITCH + c0];
                Alf[mt][2] = *(const u32*)&sAlo[r0 * SPITCH + c0 + 8];
                Alf[mt][3] = *(const u32*)&sAlo[r8 * SPITCH + c0 + 8];
            }
            #pragma unroll
            for (int nt = 0; nt < 4; nt++) {
                const int rn = warp_n * 32 + nt * 8 + g;
                const int c0 = ks + cp;
                Bhf[nt][0] = *(const u32*)&sBhi[rn * SPITCH + c0];
                Bhf[nt][1] = *(const u32*)&sBhi[rn * SPITCH + c0 + 8];
                Blf[nt][0] = *(const u32*)&sBlo[rn * SPITCH + c0];
                Blf[nt][1] = *(const u32*)&sBlo[rn * SPITCH + c0 + 8];
            }
            #pragma unroll
            for (int mt = 0; mt < 4; mt++) {
                #pragma unroll
                for (int nt = 0; nt < 4; nt++) {
                    mma_bf16(acc[mt][nt], Ahf[mt], Bhf[nt]);
                    mma_bf16(acc[mt][nt], Ahf[mt], Blf[nt]);
                    mma_bf16(acc[mt][nt], Alf[mt], Bhf[nt]);
                }
            }
        }
    }

    // ---- epilogue: distance mask, write scores[:,1:] and labels[:,1:]=0 ----
    int rX[8], rY[8], rB[8], rI[8];
    #pragma unroll
    for (int idx = 0; idx < 8; idx++) {
        int mt = idx >> 1;
        int h  = idx & 1;
        int i  = m0 + warp_m * 64 + mt * 16 + g + h * 8;
        rI[idx] = (i < NPTS) ? i : -1;
        int iw = (i < NPTS) ? i : 0;
        rX[idx] = g_xy2x[iw];
        rY[idx] = g_xy2y[iw];
        rB[idx] = iw / NPB;
    }
    int cX[8], cY[8], cB[8], cJ[8];
    #pragma unroll
    for (int idx = 0; idx < 8; idx++) {
        int nt = idx >> 1;
        int e  = idx & 1;
        int j  = n0 + warp_n * 32 + nt * 8 + cp + e;
        cJ[idx] = (j < NPTS) ? j : -1;
        int jw = (j < NPTS) ? j : 0;
        cX[idx] = g_xd[jw];
        cY[idx] = g_yd[jw];
        cB[idx] = jw / NPB;
    }

    #pragma unroll
    for (int mt = 0; mt < 4; mt++) {
        #pragma unroll
        for (int nt = 0; nt < 4; nt++) {
            #pragma unroll
            for (int r = 0; r < 4; r++) {
                int ridx = mt * 2 + (r >> 1);
                int cidx = nt * 2 + (r & 1);
                int i = rI[ridx];
                int j = cJ[cidx];
                if (i < 0 || j < 0) continue;
                int dx = cX[cidx] - rX[ridx];
                int dy = cY[cidx] - rY[ridx];
                int dis2 = dx * dx + dy * dy + ((cB[cidx] != rB[ridx]) ? 4 : 0);
                float vout = (dis2 < 4) ? 0.f : acc[mt][nt][r];
                size_t o = (size_t)i * SCOLS + 1 + j;
                out_scores[o] = vout;
                out_lab[o] = 0.0f;
            }
        }
    }
}

// ---------------- launch ----------------------------------------------------
extern "C" void kernel_launch(void* const* d_in, const int* in_sizes, int n_in,
                              void* d_out, int out_size)
{
    const float* des1  = (const float*)d_in[0];
    const float* det1  = (const float*)d_in[1];
    const float* qlt1  = (const float*)d_in[2];
    const float* des2  = (const float*)d_in[3];
    const float* det2  = (const float*)d_in[4];
    const float* qlt2  = (const float*)d_in[5];
    const float* aflow = (const float*)d_in[6];

    float* out        = (float*)d_out;
    float* out_scores = out;                                     // (3600, 3601)
    float* out_lab    = out + (size_t)NPTS * SCOLS;              // (3600, 3601)
    float* out_mask   = out_lab + (size_t)NPTS * SCOLS;          // (4, 900)
    float* out_qlt    = out_mask + NPTS;                         // (3600, 1)

    dim3 gs(NPTS, 2);
    k_sample<<<gs, 256>>>(det1, des1, det2, des2);

    k_match<<<NPTS, 128>>>(des2, aflow, qlt1, qlt2, out_scores, out_lab, out_mask, out_qlt);

    dim3 gg((NPTS + 127) / 128, (NPTS + 127) / 128);
    k_gemm<<<gg, 256>>>(out_scores, out_lab);
}